// round 8
// baseline (speedup 1.0000x reference)
#include <cuda_runtime.h>
#include <cuda_bf16.h>
#include <stdint.h>

#define NN 50000
#define NE 600000
#define SCAN_BLOCKS ((NN + 1 + 1023) / 1024)   // 49

// ---- static device scratch ----
__device__ int   g_deg[NN + 1];
__device__ int   g_off[NN + 1];
__device__ int   g_cur[NN];
__device__ int   g_srcs[NE];
__device__ int   g_bsums[64];
__device__ float g_bufA[NN * 256];
__device__ float g_bufB[NN * 128];
__device__ float g_bufC[NN * 128];
// 5 prepped weight tiles (W0,W1,W2, Wm1[:,0:128], Wm1[:,128:256]) transposed to
// Wt[n][k] row-major bf16 (hi and lo split), 128x128 each
__device__ __nv_bfloat16 g_Bhi[5 * 16384];
__device__ __nv_bfloat16 g_Blo[5 * 16384];

// ===================== warp MMA helpers (base-target safe: sm_80+) =====================
__device__ __forceinline__ uint32_t smem_u32(const void* p) {
    uint32_t a;
    asm("{ .reg .u64 t; cvta.to.shared.u64 t, %1; cvt.u32.u64 %0, t; }" : "=r"(a) : "l"(p));
    return a;
}
__device__ __forceinline__ void ldsm_x4(uint32_t* a, uint32_t addr) {
    asm volatile("ldmatrix.sync.aligned.m8n8.x4.shared.b16 {%0,%1,%2,%3}, [%4];"
                 : "=r"(a[0]), "=r"(a[1]), "=r"(a[2]), "=r"(a[3]) : "r"(addr));
}
__device__ __forceinline__ void ldsm_x2(uint32_t* b, uint32_t addr) {
    asm volatile("ldmatrix.sync.aligned.m8n8.x2.shared.b16 {%0,%1}, [%2];"
                 : "=r"(b[0]), "=r"(b[1]) : "r"(addr));
}
__device__ __forceinline__ void mma_bf16(float* c, const uint32_t* a, const uint32_t* b) {
    asm volatile("mma.sync.aligned.m16n8k16.row.col.f32.bf16.bf16.f32 "
                 "{%0,%1,%2,%3}, {%4,%5,%6,%7}, {%8,%9}, {%0,%1,%2,%3};"
                 : "+f"(c[0]), "+f"(c[1]), "+f"(c[2]), "+f"(c[3])
                 : "r"(a[0]), "r"(a[1]), "r"(a[2]), "r"(a[3]), "r"(b[0]), "r"(b[1]));
}

// ===================== CSR build =====================
__global__ void zero_kernel(int* __restrict__ deg) {
    int i = blockIdx.x * blockDim.x + threadIdx.x;
    if (i <= NN) deg[i] = 0;
}
__global__ void hist_kernel(const int* __restrict__ dst, int* __restrict__ deg) {
    int e = blockIdx.x * blockDim.x + threadIdx.x;
    if (e < NE) atomicAdd(&deg[dst[e]], 1);
}

// ---- multi-block exclusive scan over NN+1 elements ----
__global__ void blockscan_kernel(const int* __restrict__ deg, int* __restrict__ off,
                                 int* __restrict__ bsums) {
    __shared__ int wsum[32];
    int i = blockIdx.x * 1024 + threadIdx.x;
    int v = (i < NN) ? deg[i] : 0;
    int lane = threadIdx.x & 31, w = threadIdx.x >> 5;
    int inc = v;
    #pragma unroll
    for (int o = 1; o < 32; o <<= 1) {
        int t = __shfl_up_sync(0xffffffffu, inc, o);
        if (lane >= o) inc += t;
    }
    if (lane == 31) wsum[w] = inc;
    __syncthreads();
    if (w == 0) {
        int s = wsum[lane];
        #pragma unroll
        for (int o = 1; o < 32; o <<= 1) {
            int t = __shfl_up_sync(0xffffffffu, s, o);
            if (lane >= o) s += t;
        }
        wsum[lane] = s;
    }
    __syncthreads();
    int prefix = (w > 0) ? wsum[w - 1] : 0;
    if (i <= NN) off[i] = prefix + inc - v;
    if (threadIdx.x == 1023) bsums[blockIdx.x] = wsum[31];
}
__global__ void scanb_kernel(int* __restrict__ bsums) {
    __shared__ int sm[64];
    int lane = threadIdx.x;
    int v = (lane < SCAN_BLOCKS) ? bsums[lane] : 0;
    sm[lane] = v;
    __syncthreads();
    for (int o = 1; o < 64; o <<= 1) {
        int t = (lane >= o) ? sm[lane - o] : 0;
        __syncthreads();
        sm[lane] += t;
        __syncthreads();
    }
    if (lane < SCAN_BLOCKS) bsums[lane] = sm[lane] - v;
}
__global__ void addoff_kernel(int* __restrict__ off, const int* __restrict__ bsums,
                              int* __restrict__ cur) {
    int i = blockIdx.x * 1024 + threadIdx.x;
    if (i <= NN) {
        int v = off[i] + bsums[blockIdx.x];
        off[i] = v;
        if (i < NN) cur[i] = v;      // scatter cursor starts at row offset
    }
}
__global__ void scatter_kernel(const int* __restrict__ src, const int* __restrict__ dst,
                               int* __restrict__ cur, int* __restrict__ srcs) {
    int e = blockIdx.x * blockDim.x + threadIdx.x;
    if (e < NE) {
        int p = atomicAdd(&cur[dst[e]], 1);
        srcs[p] = src[e];
    }
}

// ===================== weight prep: transpose + bf16 hi/lo split =====================
__global__ void prep_w_kernel(const float* __restrict__ W0, const float* __restrict__ W1,
                              const float* __restrict__ W2, const float* __restrict__ Wm1,
                              __nv_bfloat16* __restrict__ bhi, __nv_bfloat16* __restrict__ blo) {
    int idx = blockIdx.x * blockDim.x + threadIdx.x;
    if (idx >= 5 * 16384) return;
    int t = idx >> 14;
    int e = idx & 16383;
    int n = e >> 7, k = e & 127;
    float w;
    if (t == 0)      w = W0[k * 128 + n];
    else if (t == 1) w = W1[k * 128 + n];
    else if (t == 2) w = W2[k * 128 + n];
    else             w = Wm1[k * 256 + (t - 3) * 128 + n];
    __nv_bfloat16 h = __float2bfloat16(w);
    __nv_bfloat16 l = __float2bfloat16(w - __bfloat162float(h));
    bhi[idx] = h;
    blo[idx] = l;
}

// ===================== fused (gather +) tensor-core GEMM =====================
// out[rows, colOff:+128] = relu( (fuseAgg ? x + sum_nbr x : A)[rows,128] @ Wt^T + b )
// CTA: 128 rows x 128 cols, K=128 resident, 512 threads (16 warps, 4x4 warp grid,
// warp tile 32x32 = 2x4 m16n8k16 tiles). bf16 hi/lo 3-term split on tensor pipe.
#define LDA    136                 // padded bf16 stride
#define A_HI   0
#define A_LO   34816
#define B_HI   69632
#define B_LO   104448
#define SM_BS  139264
#define SM_BYTES (139264 + 512)

__global__ void __launch_bounds__(512, 1)
gin_gemm_kernel(const float* __restrict__ A,
                const int* __restrict__ off, const int* __restrict__ srcs,
                const __nv_bfloat16* __restrict__ gBhi,
                const __nv_bfloat16* __restrict__ gBlo,
                const float* __restrict__ bias,
                float* __restrict__ out,
                int tile0, int outCols, int fuseAgg) {
    extern __shared__ char smem[];
    const int tid  = threadIdx.x;
    const int wid  = tid >> 5;
    const int lane = tid & 31;
    const int t = tile0 + blockIdx.y;
    const int colOff = blockIdx.y * 128;
    const int rowBase = blockIdx.x * 128;

    // ---- B tiles first (independent of gather; overlaps its latency) ----
    {
        const uint4* shi = reinterpret_cast<const uint4*>(gBhi + t * 16384);
        const uint4* slo = reinterpret_cast<const uint4*>(gBlo + t * 16384);
        #pragma unroll
        for (int i = 0; i < 4; i++) {
            int lin = tid + i * 512;          // 2048 uint4
            int n = lin >> 4, q = lin & 15;
            int boff = n * (LDA * 2) + q * 16;
            *reinterpret_cast<uint4*>(smem + B_HI + boff) = shi[lin];
            *reinterpret_cast<uint4*>(smem + B_LO + boff) = slo[lin];
        }
        if (tid < 128) reinterpret_cast<float*>(smem + SM_BS)[tid] = bias[colOff + tid];
    }

    // ---- A tile: gather+sum (GIN) or plain load; fp32 -> bf16 hi/lo into smem ----
    const float4* A4 = reinterpret_cast<const float4*>(A);
    if (fuseAgg) {
        // warp per node-slice: warp handles 8 rows, lane owns one float4 (4 cols)
        #pragma unroll
        for (int i = 0; i < 8; i++) {
            int r = wid * 8 + i;
            int node = rowBase + r;
            float4 acc  = make_float4(0.f, 0.f, 0.f, 0.f);
            if (node < NN) {
                acc = A4[node * 32 + lane];
                int s = off[node], e = off[node + 1];
                float4 acc2 = make_float4(0.f, 0.f, 0.f, 0.f);
                int j = s;
                for (; j + 2 <= e; j += 2) {
                    int sc0 = __ldg(&srcs[j]);
                    int sc1 = __ldg(&srcs[j + 1]);
                    float4 v0 = A4[sc0 * 32 + lane];
                    float4 v1 = A4[sc1 * 32 + lane];
                    acc.x  += v0.x; acc.y  += v0.y; acc.z  += v0.z; acc.w  += v0.w;
                    acc2.x += v1.x; acc2.y += v1.y; acc2.z += v1.z; acc2.w += v1.w;
                }
                if (j < e) {
                    int sc = __ldg(&srcs[j]);
                    float4 v = A4[sc * 32 + lane];
                    acc.x += v.x; acc.y += v.y; acc.z += v.z; acc.w += v.w;
                }
                acc.x += acc2.x; acc.y += acc2.y; acc.z += acc2.z; acc.w += acc2.w;
            }
            __nv_bfloat162 h0 = __floats2bfloat162_rn(acc.x, acc.y);
            __nv_bfloat162 h1 = __floats2bfloat162_rn(acc.z, acc.w);
            float2 hf0 = __bfloat1622float2(h0);
            float2 hf1 = __bfloat1622float2(h1);
            __nv_bfloat162 l0 = __floats2bfloat162_rn(acc.x - hf0.x, acc.y - hf0.y);
            __nv_bfloat162 l1 = __floats2bfloat162_rn(acc.z - hf1.x, acc.w - hf1.y);
            uint2 hv = make_uint2(reinterpret_cast<uint32_t&>(h0), reinterpret_cast<uint32_t&>(h1));
            uint2 lv = make_uint2(reinterpret_cast<uint32_t&>(l0), reinterpret_cast<uint32_t&>(l1));
            int boff = r * (LDA * 2) + lane * 8;
            *reinterpret_cast<uint2*>(smem + A_HI + boff) = hv;
            *reinterpret_cast<uint2*>(smem + A_LO + boff) = lv;
        }
    } else {
        #pragma unroll
        for (int i = 0; i < 8; i++) {
            int lin = tid + i * 512;          // 4096 float4
            int r   = lin >> 5;
            int c4  = lin & 31;
            int gr  = rowBase + r;
            float4 f = (gr < NN) ? A4[gr * 32 + c4] : make_float4(0.f, 0.f, 0.f, 0.f);
            __nv_bfloat162 h0 = __floats2bfloat162_rn(f.x, f.y);
            __nv_bfloat162 h1 = __floats2bfloat162_rn(f.z, f.w);
            float2 hf0 = __bfloat1622float2(h0);
            float2 hf1 = __bfloat1622float2(h1);
            __nv_bfloat162 l0 = __floats2bfloat162_rn(f.x - hf0.x, f.y - hf0.y);
            __nv_bfloat162 l1 = __floats2bfloat162_rn(f.z - hf1.x, f.w - hf1.y);
            uint2 hv = make_uint2(reinterpret_cast<uint32_t&>(h0), reinterpret_cast<uint32_t&>(h1));
            uint2 lv = make_uint2(reinterpret_cast<uint32_t&>(l0), reinterpret_cast<uint32_t&>(l1));
            int boff = r * (LDA * 2) + c4 * 8;
            *reinterpret_cast<uint2*>(smem + A_HI + boff) = hv;
            *reinterpret_cast<uint2*>(smem + A_LO + boff) = lv;
        }
    }
    __syncthreads();

    // ---- warp MMA mainloop: warp tile 32x32 (2 mt x 4 nt) ----
    const int wm = (wid & 3) * 32;
    const int wn = (wid >> 2) * 32;
    float acc[2][4][4];
    #pragma unroll
    for (int mt = 0; mt < 2; mt++)
        #pragma unroll
        for (int nt = 0; nt < 4; nt++)
            #pragma unroll
            for (int j = 0; j < 4; j++) acc[mt][nt][j] = 0.f;

    const uint32_t sb = smem_u32(smem);
    const uint32_t aBaseHi = sb + A_HI + (wm + (lane & 15)) * (LDA * 2) + (lane >> 4) * 16;
    const uint32_t aBaseLo = aBaseHi + (A_LO - A_HI);
    const uint32_t bBaseHi = sb + B_HI + (wn + (lane & 7)) * (LDA * 2) + ((lane >> 3) & 1) * 16;
    const uint32_t bBaseLo = bBaseHi + (B_LO - B_HI);

    #pragma unroll
    for (int ks = 0; ks < 8; ks++) {
        uint32_t bh[4][2], bl[4][2];
        #pragma unroll
        for (int nt = 0; nt < 4; nt++) {
            ldsm_x2(bh[nt], bBaseHi + nt * 8 * (LDA * 2) + ks * 32);
            ldsm_x2(bl[nt], bBaseLo + nt * 8 * (LDA * 2) + ks * 32);
        }
        #pragma unroll
        for (int mt = 0; mt < 2; mt++) {
            uint32_t ah[4], al[4];
            ldsm_x4(ah, aBaseHi + mt * 16 * (LDA * 2) + ks * 32);
            ldsm_x4(al, aBaseLo + mt * 16 * (LDA * 2) + ks * 32);
            #pragma unroll
            for (int nt = 0; nt < 4; nt++) {
                mma_bf16(acc[mt][nt], ah, bh[nt]);
                mma_bf16(acc[mt][nt], ah, bl[nt]);
                mma_bf16(acc[mt][nt], al, bh[nt]);
            }
        }
    }

    // ---- epilogue: bias + relu, fp32 store ----
    const float* bs = reinterpret_cast<const float*>(smem + SM_BS);
    #pragma unroll
    for (int mt = 0; mt < 2; mt++) {
        #pragma unroll
        for (int nt = 0; nt < 4; nt++) {
            int lc = wn + nt * 8 + (lane & 3) * 2;
            int r0 = rowBase + wm + mt * 16 + (lane >> 2);
            float b0 = bs[lc], b1 = bs[lc + 1];
            int c = colOff + lc;
            if (r0 < NN) {
                float2 v;
                v.x = fmaxf(acc[mt][nt][0] + b0, 0.f);
                v.y = fmaxf(acc[mt][nt][1] + b1, 0.f);
                *reinterpret_cast<float2*>(out + (size_t)r0 * outCols + c) = v;
            }
            if (r0 + 8 < NN) {
                float2 v;
                v.x = fmaxf(acc[mt][nt][2] + b0, 0.f);
                v.y = fmaxf(acc[mt][nt][3] + b1, 0.f);
                *reinterpret_cast<float2*>(out + (size_t)(r0 + 8) * outCols + c) = v;
            }
        }
    }
}

// ===================== head =====================
__global__ void head_kernel(const float* __restrict__ A, const float* __restrict__ W,
                            const float* __restrict__ b, float* __restrict__ out) {
    __shared__ float Ws[256 * 10];
    __shared__ float bs[10];
    for (int i = threadIdx.x; i < 2560; i += blockDim.x) Ws[i] = W[i];
    if (threadIdx.x < 10) bs[threadIdx.x] = b[threadIdx.x];
    __syncthreads();

    int gw   = (blockIdx.x * blockDim.x + threadIdx.x) >> 5;
    int lane = threadIdx.x & 31;
    if (gw >= NN) return;

    float acc[10];
    #pragma unroll
    for (int c = 0; c < 10; c++) acc[c] = 0.f;
    for (int k = lane; k < 256; k += 32) {
        float a = A[gw * 256 + k];
        #pragma unroll
        for (int c = 0; c < 10; c++) acc[c] += a * Ws[k * 10 + c];
    }
    #pragma unroll
    for (int c = 0; c < 10; c++) {
        #pragma unroll
        for (int o = 16; o; o >>= 1) acc[c] += __shfl_down_sync(0xffffffffu, acc[c], o);
    }
    if (lane == 0) {
        #pragma unroll
        for (int c = 0; c < 10; c++) out[gw * 10 + c] = acc[c] + bs[c];
    }
}

// ===================== host =====================
extern "C" void kernel_launch(void* const* d_in, const int* in_sizes, int n_in,
                              void* d_out, int out_size) {
    const float* x   = (const float*)d_in[0];
    const int*   ei  = (const int*)d_in[1];
    const float* W0  = (const float*)d_in[2];
    const float* b0  = (const float*)d_in[3];
    const float* W1  = (const float*)d_in[4];
    const float* b1  = (const float*)d_in[5];
    const float* W2  = (const float*)d_in[6];
    const float* b2  = (const float*)d_in[7];
    const float* Wm1 = (const float*)d_in[8];
    const float* bm1 = (const float*)d_in[9];
    const float* Wm2 = (const float*)d_in[10];
    const float* bm2 = (const float*)d_in[11];
    const int* src = ei;
    const int* dst = ei + NE;

    int *deg, *off, *cur, *srcs, *bsums;
    float *bufA, *bufB, *bufC;
    __nv_bfloat16 *bhi, *blo;
    cudaGetSymbolAddress((void**)&deg,   g_deg);
    cudaGetSymbolAddress((void**)&off,   g_off);
    cudaGetSymbolAddress((void**)&cur,   g_cur);
    cudaGetSymbolAddress((void**)&srcs,  g_srcs);
    cudaGetSymbolAddress((void**)&bsums, g_bsums);
    cudaGetSymbolAddress((void**)&bufA,  g_bufA);
    cudaGetSymbolAddress((void**)&bufB,  g_bufB);
    cudaGetSymbolAddress((void**)&bufC,  g_bufC);
    cudaGetSymbolAddress((void**)&bhi,   g_Bhi);
    cudaGetSymbolAddress((void**)&blo,   g_Blo);

    cudaFuncSetAttribute(gin_gemm_kernel,
                         cudaFuncAttributeMaxDynamicSharedMemorySize, SM_BYTES);

    // weight prep + CSR build
    prep_w_kernel<<<(5 * 16384 + 255) / 256, 256>>>(W0, W1, W2, Wm1, bhi, blo);
    zero_kernel<<<(NN + 1 + 255) / 256, 256>>>(deg);
    hist_kernel<<<(NE + 255) / 256, 256>>>(dst, deg);
    blockscan_kernel<<<SCAN_BLOCKS, 1024>>>(deg, off, bsums);
    scanb_kernel<<<1, 64>>>(bsums);
    addoff_kernel<<<SCAN_BLOCKS, 1024>>>(off, bsums, cur);
    scatter_kernel<<<(NE + 255) / 256, 256>>>(src, dst, cur, srcs);

    const int warpBlocks = (NN * 32 + 255) / 256;
    const int gemmBlocks = (NN + 127) / 128;   // 391

    // fused GIN layers: gather + GEMM + bias + relu
    gin_gemm_kernel<<<dim3(gemmBlocks, 1), 512, SM_BYTES>>>(x,    off, srcs, bhi, blo, b0, bufB, 0, 128, 1);
    gin_gemm_kernel<<<dim3(gemmBlocks, 1), 512, SM_BYTES>>>(bufB, off, srcs, bhi, blo, b1, bufC, 1, 128, 1);
    gin_gemm_kernel<<<dim3(gemmBlocks, 1), 512, SM_BYTES>>>(bufC, off, srcs, bhi, blo, b2, bufB, 2, 128, 1);
    // MLP hidden [N,256] as two 128-col tiles (no aggregation)
    gin_gemm_kernel<<<dim3(gemmBlocks, 2), 512, SM_BYTES>>>(bufB, off, srcs, bhi, blo, bm1, bufA, 3, 256, 0);
    // head
    head_kernel<<<warpBlocks, 256>>>(bufA, Wm2, bm2, (float*)d_out);
}

// round 12
// speedup vs baseline: 1.0568x; 1.0568x over previous
#include <cuda_runtime.h>
#include <cuda_bf16.h>
#include <stdint.h>

#define NN 50000
#define NE 600000
#define SCAN_BLOCKS ((NN + 1 + 1023) / 1024)   // 49

// ---- static device scratch ----
__device__ int   g_deg[NN + 1];
__device__ int   g_off[NN + 1];
__device__ int   g_cur[NN];
__device__ int   g_srcs[NE];
__device__ int   g_bsums[64];
__device__ float g_bufA[NN * 256];
__device__ float g_bufB[NN * 128];
// 5 prepped weight tiles (W0,W1,W2, Wm1[:,0:128], Wm1[:,128:256]) transposed to
// Wt[n][k] row-major bf16 (hi and lo split), 128x128 each
__device__ __nv_bfloat16 g_Bhi[5 * 16384];
__device__ __nv_bfloat16 g_Blo[5 * 16384];

// ===================== warp MMA helpers (base-target safe: sm_80+) =====================
__device__ __forceinline__ uint32_t smem_u32(const void* p) {
    uint32_t a;
    asm("{ .reg .u64 t; cvta.to.shared.u64 t, %1; cvt.u32.u64 %0, t; }" : "=r"(a) : "l"(p));
    return a;
}
__device__ __forceinline__ void ldsm_x4(uint32_t* a, uint32_t addr) {
    asm volatile("ldmatrix.sync.aligned.m8n8.x4.shared.b16 {%0,%1,%2,%3}, [%4];"
                 : "=r"(a[0]), "=r"(a[1]), "=r"(a[2]), "=r"(a[3]) : "r"(addr));
}
__device__ __forceinline__ void ldsm_x2(uint32_t* b, uint32_t addr) {
    asm volatile("ldmatrix.sync.aligned.m8n8.x2.shared.b16 {%0,%1}, [%2];"
                 : "=r"(b[0]), "=r"(b[1]) : "r"(addr));
}
__device__ __forceinline__ void mma_bf16(float* c, const uint32_t* a, const uint32_t* b) {
    asm volatile("mma.sync.aligned.m16n8k16.row.col.f32.bf16.bf16.f32 "
                 "{%0,%1,%2,%3}, {%4,%5,%6,%7}, {%8,%9}, {%0,%1,%2,%3};"
                 : "+f"(c[0]), "+f"(c[1]), "+f"(c[2]), "+f"(c[3])
                 : "r"(a[0]), "r"(a[1]), "r"(a[2]), "r"(a[3]), "r"(b[0]), "r"(b[1]));
}

// ===================== CSR build =====================
__global__ void zero_kernel(int* __restrict__ deg) {
    int i = blockIdx.x * blockDim.x + threadIdx.x;
    if (i <= NN) deg[i] = 0;
}
__global__ void hist_kernel(const int* __restrict__ dst, int* __restrict__ deg) {
    int e = blockIdx.x * blockDim.x + threadIdx.x;
    if (e < NE) atomicAdd(&deg[dst[e]], 1);
}
__global__ void blockscan_kernel(const int* __restrict__ deg, int* __restrict__ off,
                                 int* __restrict__ bsums) {
    __shared__ int wsum[32];
    int i = blockIdx.x * 1024 + threadIdx.x;
    int v = (i < NN) ? deg[i] : 0;
    int lane = threadIdx.x & 31, w = threadIdx.x >> 5;
    int inc = v;
    #pragma unroll
    for (int o = 1; o < 32; o <<= 1) {
        int t = __shfl_up_sync(0xffffffffu, inc, o);
        if (lane >= o) inc += t;
    }
    if (lane == 31) wsum[w] = inc;
    __syncthreads();
    if (w == 0) {
        int s = wsum[lane];
        #pragma unroll
        for (int o = 1; o < 32; o <<= 1) {
            int t = __shfl_up_sync(0xffffffffu, s, o);
            if (lane >= o) s += t;
        }
        wsum[lane] = s;
    }
    __syncthreads();
    int prefix = (w > 0) ? wsum[w - 1] : 0;
    if (i <= NN) off[i] = prefix + inc - v;
    if (threadIdx.x == 1023) bsums[blockIdx.x] = wsum[31];
}
__global__ void scanb_kernel(int* __restrict__ bsums) {
    __shared__ int sm[64];
    int lane = threadIdx.x;
    int v = (lane < SCAN_BLOCKS) ? bsums[lane] : 0;
    sm[lane] = v;
    __syncthreads();
    for (int o = 1; o < 64; o <<= 1) {
        int t = (lane >= o) ? sm[lane - o] : 0;
        __syncthreads();
        sm[lane] += t;
        __syncthreads();
    }
    if (lane < SCAN_BLOCKS) bsums[lane] = sm[lane] - v;
}
__global__ void addoff_kernel(int* __restrict__ off, const int* __restrict__ bsums,
                              int* __restrict__ cur) {
    int i = blockIdx.x * 1024 + threadIdx.x;
    if (i <= NN) {
        int v = off[i] + bsums[blockIdx.x];
        off[i] = v;
        if (i < NN) cur[i] = v;
    }
}
__global__ void scatter_kernel(const int* __restrict__ src, const int* __restrict__ dst,
                               int* __restrict__ cur, int* __restrict__ srcs) {
    int e = blockIdx.x * blockDim.x + threadIdx.x;
    if (e < NE) {
        int p = atomicAdd(&cur[dst[e]], 1);
        srcs[p] = src[e];
    }
}

// ===================== GIN aggregate =====================
__global__ void agg_kernel(const float4* __restrict__ x, const int* __restrict__ off,
                           const int* __restrict__ srcs, float4* __restrict__ out) {
    int gw   = (blockIdx.x * blockDim.x + threadIdx.x) >> 5;
    int lane = threadIdx.x & 31;
    if (gw >= NN) return;
    int s = off[gw], e = off[gw + 1];
    float4 acc = x[gw * 32 + lane];
    #pragma unroll 2
    for (int i = s; i < e; i++) {
        int sc   = __ldg(&srcs[i]);
        float4 v = x[sc * 32 + lane];
        acc.x += v.x; acc.y += v.y; acc.z += v.z; acc.w += v.w;
    }
    out[gw * 32 + lane] = acc;
}

// ===================== weight prep: transpose + bf16 hi/lo split =====================
__global__ void prep_w_kernel(const float* __restrict__ W0, const float* __restrict__ W1,
                              const float* __restrict__ W2, const float* __restrict__ Wm1,
                              __nv_bfloat16* __restrict__ bhi, __nv_bfloat16* __restrict__ blo) {
    int idx = blockIdx.x * blockDim.x + threadIdx.x;
    if (idx >= 5 * 16384) return;
    int t = idx >> 14;
    int e = idx & 16383;
    int n = e >> 7, k = e & 127;
    float w;
    if (t == 0)      w = W0[k * 128 + n];
    else if (t == 1) w = W1[k * 128 + n];
    else if (t == 2) w = W2[k * 128 + n];
    else             w = Wm1[k * 256 + (t - 3) * 128 + n];
    __nv_bfloat16 h = __float2bfloat16(w);
    __nv_bfloat16 l = __float2bfloat16(w - __bfloat162float(h));
    bhi[idx] = h;
    blo[idx] = l;
}

// ===================== tensor-core GEMM (mma.sync bf16 hi/lo split), BM=256 =====================
// out[rows, colOff:+128] = relu(A[rows,128] @ Wt^T + b)
// CTA: 256 rows x 128 cols, K=128 resident, 512 threads (16 warps, 4x4 warp grid,
// warp tile 64x32 = 4x4 m16n8k16 tiles).
#define LDA    136                 // padded bf16 stride (272 B)
#define A_HI   0
#define A_LO   69632
#define B_HI   139264
#define B_LO   174080
#define SM_BS  208896
#define SM_BYTES (208896 + 512 + 128)

__global__ void __launch_bounds__(512, 1)
gemm_tc_kernel(const float* __restrict__ A,
               const __nv_bfloat16* __restrict__ gBhi,
               const __nv_bfloat16* __restrict__ gBlo,
               const float* __restrict__ bias,
               float* __restrict__ out,
               int tile0, int outCols) {
    extern __shared__ char smem[];
    const int tid  = threadIdx.x;
    const int wid  = tid >> 5;
    const int lane = tid & 31;
    const int t = tile0 + blockIdx.y;
    const int colOff = blockIdx.y * 128;
    const int rowBase = blockIdx.x * 256;

    // ---- load A tile (256x128 fp32 -> bf16 hi/lo, padded smem) ----
    {
        const float4* A4 = reinterpret_cast<const float4*>(A);
        #pragma unroll
        for (int i = 0; i < 16; i++) {
            int lin = tid + i * 512;          // 8192 float4
            int r   = lin >> 5;
            int c4  = lin & 31;
            int gr  = rowBase + r;
            float4 f = (gr < NN) ? A4[gr * 32 + c4] : make_float4(0.f, 0.f, 0.f, 0.f);
            __nv_bfloat162 h0 = __floats2bfloat162_rn(f.x, f.y);
            __nv_bfloat162 h1 = __floats2bfloat162_rn(f.z, f.w);
            float2 hf0 = __bfloat1622float2(h0);
            float2 hf1 = __bfloat1622float2(h1);
            __nv_bfloat162 l0 = __floats2bfloat162_rn(f.x - hf0.x, f.y - hf0.y);
            __nv_bfloat162 l1 = __floats2bfloat162_rn(f.z - hf1.x, f.w - hf1.y);
            uint2 hv = make_uint2(reinterpret_cast<uint32_t&>(h0), reinterpret_cast<uint32_t&>(h1));
            uint2 lv = make_uint2(reinterpret_cast<uint32_t&>(l0), reinterpret_cast<uint32_t&>(l1));
            int boff = r * (LDA * 2) + c4 * 8;
            *reinterpret_cast<uint2*>(smem + A_HI + boff) = hv;
            *reinterpret_cast<uint2*>(smem + A_LO + boff) = lv;
        }
    }
    // ---- load B tiles (prepped bf16, linear copy into padded smem) ----
    {
        const uint4* shi = reinterpret_cast<const uint4*>(gBhi + t * 16384);
        const uint4* slo = reinterpret_cast<const uint4*>(gBlo + t * 16384);
        #pragma unroll
        for (int i = 0; i < 4; i++) {
            int lin = tid + i * 512;          // 2048 uint4
            int n = lin >> 4, q = lin & 15;
            int boff = n * (LDA * 2) + q * 16;
            *reinterpret_cast<uint4*>(smem + B_HI + boff) = shi[lin];
            *reinterpret_cast<uint4*>(smem + B_LO + boff) = slo[lin];
        }
        if (tid < 128) reinterpret_cast<float*>(smem + SM_BS)[tid] = bias[colOff + tid];
    }
    __syncthreads();

    // ---- warp MMA mainloop: 16 warps, warp tile 64x32 ----
    const int wm = (wid & 3) * 64;
    const int wn = (wid >> 2) * 32;
    float acc[4][4][4];
    #pragma unroll
    for (int mt = 0; mt < 4; mt++)
        #pragma unroll
        for (int nt = 0; nt < 4; nt++)
            #pragma unroll
            for (int j = 0; j < 4; j++) acc[mt][nt][j] = 0.f;

    const uint32_t sb = smem_u32(smem);
    const uint32_t aBaseHi = sb + A_HI + (wm + (lane & 15)) * (LDA * 2) + (lane >> 4) * 16;
    const uint32_t aBaseLo = aBaseHi + (A_LO - A_HI);
    const uint32_t bBaseHi = sb + B_HI + (wn + (lane & 7)) * (LDA * 2) + ((lane >> 3) & 1) * 16;
    const uint32_t bBaseLo = bBaseHi + (B_LO - B_HI);

    #pragma unroll
    for (int ks = 0; ks < 8; ks++) {
        uint32_t bh[4][2], bl[4][2];
        #pragma unroll
        for (int nt = 0; nt < 4; nt++) {
            ldsm_x2(bh[nt], bBaseHi + nt * 8 * (LDA * 2) + ks * 32);
            ldsm_x2(bl[nt], bBaseLo + nt * 8 * (LDA * 2) + ks * 32);
        }
        #pragma unroll
        for (int mt = 0; mt < 4; mt++) {
            uint32_t ah[4], al[4];
            ldsm_x4(ah, aBaseHi + mt * 16 * (LDA * 2) + ks * 32);
            ldsm_x4(al, aBaseLo + mt * 16 * (LDA * 2) + ks * 32);
            #pragma unroll
            for (int nt = 0; nt < 4; nt++) {
                mma_bf16(acc[mt][nt], ah, bh[nt]);
                mma_bf16(acc[mt][nt], ah, bl[nt]);
                mma_bf16(acc[mt][nt], al, bh[nt]);
            }
        }
    }

    // ---- epilogue: bias + relu, fp32 store ----
    const float* bs = reinterpret_cast<const float*>(smem + SM_BS);
    #pragma unroll
    for (int mt = 0; mt < 4; mt++) {
        #pragma unroll
        for (int nt = 0; nt < 4; nt++) {
            int lc = wn + nt * 8 + (lane & 3) * 2;
            int r0 = rowBase + wm + mt * 16 + (lane >> 2);
            float b0 = bs[lc], b1 = bs[lc + 1];
            int c = colOff + lc;
            if (r0 < NN) {
                float2 v;
                v.x = fmaxf(acc[mt][nt][0] + b0, 0.f);
                v.y = fmaxf(acc[mt][nt][1] + b1, 0.f);
                *reinterpret_cast<float2*>(out + (size_t)r0 * outCols + c) = v;
            }
            if (r0 + 8 < NN) {
                float2 v;
                v.x = fmaxf(acc[mt][nt][2] + b0, 0.f);
                v.y = fmaxf(acc[mt][nt][3] + b1, 0.f);
                *reinterpret_cast<float2*>(out + (size_t)(r0 + 8) * outCols + c) = v;
            }
        }
    }
}

// ===================== head =====================
__global__ void head_kernel(const float* __restrict__ A, const float* __restrict__ W,
                            const float* __restrict__ b, float* __restrict__ out) {
    __shared__ float Ws[256 * 10];
    __shared__ float bs[10];
    for (int i = threadIdx.x; i < 2560; i += blockDim.x) Ws[i] = W[i];
    if (threadIdx.x < 10) bs[threadIdx.x] = b[threadIdx.x];
    __syncthreads();

    int gw   = (blockIdx.x * blockDim.x + threadIdx.x) >> 5;
    int lane = threadIdx.x & 31;
    if (gw >= NN) return;

    float acc[10];
    #pragma unroll
    for (int c = 0; c < 10; c++) acc[c] = 0.f;
    for (int k = lane; k < 256; k += 32) {
        float a = A[gw * 256 + k];
        #pragma unroll
        for (int c = 0; c < 10; c++) acc[c] += a * Ws[k * 10 + c];
    }
    #pragma unroll
    for (int c = 0; c < 10; c++) {
        #pragma unroll
        for (int o = 16; o; o >>= 1) acc[c] += __shfl_down_sync(0xffffffffu, acc[c], o);
    }
    if (lane == 0) {
        #pragma unroll
        for (int c = 0; c < 10; c++) out[gw * 10 + c] = acc[c] + bs[c];
    }
}

// ===================== host =====================
extern "C" void kernel_launch(void* const* d_in, const int* in_sizes, int n_in,
                              void* d_out, int out_size) {
    const float* x   = (const float*)d_in[0];
    const int*   ei  = (const int*)d_in[1];
    const float* W0  = (const float*)d_in[2];
    const float* b0  = (const float*)d_in[3];
    const float* W1  = (const float*)d_in[4];
    const float* b1  = (const float*)d_in[5];
    const float* W2  = (const float*)d_in[6];
    const float* b2  = (const float*)d_in[7];
    const float* Wm1 = (const float*)d_in[8];
    const float* bm1 = (const float*)d_in[9];
    const float* Wm2 = (const float*)d_in[10];
    const float* bm2 = (const float*)d_in[11];
    const int* src = ei;
    const int* dst = ei + NE;

    int *deg, *off, *cur, *srcs, *bsums;
    float *bufA, *bufB;
    __nv_bfloat16 *bhi, *blo;
    cudaGetSymbolAddress((void**)&deg,   g_deg);
    cudaGetSymbolAddress((void**)&off,   g_off);
    cudaGetSymbolAddress((void**)&cur,   g_cur);
    cudaGetSymbolAddress((void**)&srcs,  g_srcs);
    cudaGetSymbolAddress((void**)&bsums, g_bsums);
    cudaGetSymbolAddress((void**)&bufA,  g_bufA);
    cudaGetSymbolAddress((void**)&bufB,  g_bufB);
    cudaGetSymbolAddress((void**)&bhi,   g_Bhi);
    cudaGetSymbolAddress((void**)&blo,   g_Blo);

    cudaFuncSetAttribute(gemm_tc_kernel,
                         cudaFuncAttributeMaxDynamicSharedMemorySize, SM_BYTES);

    // weight prep + CSR build
    prep_w_kernel<<<(5 * 16384 + 255) / 256, 256>>>(W0, W1, W2, Wm1, bhi, blo);
    zero_kernel<<<(NN + 1 + 255) / 256, 256>>>(deg);
    hist_kernel<<<(NE + 255) / 256, 256>>>(dst, deg);
    blockscan_kernel<<<SCAN_BLOCKS, 1024>>>(deg, off, bsums);
    scanb_kernel<<<1, 64>>>(bsums);
    addoff_kernel<<<SCAN_BLOCKS, 1024>>>(off, bsums, cur);
    scatter_kernel<<<(NE + 255) / 256, 256>>>(src, dst, cur, srcs);

    const int warpBlocks = (NN * 32 + 255) / 256;
    const int gemmBlocks = (NN + 255) / 256;   // 196

    // layer 0
    agg_kernel<<<warpBlocks, 256>>>((const float4*)x, off, srcs, (float4*)bufA);
    gemm_tc_kernel<<<dim3(gemmBlocks, 1), 512, SM_BYTES>>>(bufA, bhi, blo, b0, bufB, 0, 128);
    // layer 1
    agg_kernel<<<warpBlocks, 256>>>((const float4*)bufB, off, srcs, (float4*)bufA);
    gemm_tc_kernel<<<dim3(gemmBlocks, 1), 512, SM_BYTES>>>(bufA, bhi, blo, b1, bufB, 1, 128);
    // layer 2
    agg_kernel<<<warpBlocks, 256>>>((const float4*)bufB, off, srcs, (float4*)bufA);
    gemm_tc_kernel<<<dim3(gemmBlocks, 1), 512, SM_BYTES>>>(bufA, bhi, blo, b2, bufB, 2, 128);
    // MLP hidden [N,256] as two 128-col tiles
    gemm_tc_kernel<<<dim3(gemmBlocks, 2), 512, SM_BYTES>>>(bufB, bhi, blo, bm1, bufA, 3, 256);
    // head
    head_kernel<<<warpBlocks, 256>>>(bufA, Wm2, bm2, (float*)d_out);
}

// round 13
// speedup vs baseline: 1.0584x; 1.0015x over previous
#include <cuda_runtime.h>
#include <cuda_bf16.h>
#include <stdint.h>

#define NN 50000
#define NE 600000
#define SCAN_BLOCKS ((NN + 1 + 1023) / 1024)   // 49

// ---- static device scratch ----
__device__ int   g_deg[NN + 1];
__device__ int   g_off[NN + 1];
__device__ int   g_cur[NN];
__device__ int   g_srcs[NE];
__device__ int   g_bsums[64];
__device__ float g_bufA[NN * 256];
__device__ float g_bufB[NN * 128];
// 5 prepped weight tiles (W0,W1,W2, Wm1[:,0:128], Wm1[:,128:256]) transposed to
// Wt[n][k] row-major bf16 (hi and lo split), 128x128 each
__device__ __nv_bfloat16 g_Bhi[5 * 16384];
__device__ __nv_bfloat16 g_Blo[5 * 16384];

// ===================== warp MMA helpers (base-target safe: sm_80+) =====================
__device__ __forceinline__ uint32_t smem_u32(const void* p) {
    uint32_t a;
    asm("{ .reg .u64 t; cvta.to.shared.u64 t, %1; cvt.u32.u64 %0, t; }" : "=r"(a) : "l"(p));
    return a;
}
__device__ __forceinline__ void ldsm_x4(uint32_t* a, uint32_t addr) {
    asm volatile("ldmatrix.sync.aligned.m8n8.x4.shared.b16 {%0,%1,%2,%3}, [%4];"
                 : "=r"(a[0]), "=r"(a[1]), "=r"(a[2]), "=r"(a[3]) : "r"(addr));
}
__device__ __forceinline__ void ldsm_x2(uint32_t* b, uint32_t addr) {
    asm volatile("ldmatrix.sync.aligned.m8n8.x2.shared.b16 {%0,%1}, [%2];"
                 : "=r"(b[0]), "=r"(b[1]) : "r"(addr));
}
__device__ __forceinline__ void mma_bf16(float* c, const uint32_t* a, const uint32_t* b) {
    asm volatile("mma.sync.aligned.m16n8k16.row.col.f32.bf16.bf16.f32 "
                 "{%0,%1,%2,%3}, {%4,%5,%6,%7}, {%8,%9}, {%0,%1,%2,%3};"
                 : "+f"(c[0]), "+f"(c[1]), "+f"(c[2]), "+f"(c[3])
                 : "r"(a[0]), "r"(a[1]), "r"(a[2]), "r"(a[3]), "r"(b[0]), "r"(b[1]));
}

// ===================== CSR build =====================
__global__ void zero_kernel(int* __restrict__ deg) {
    int i = blockIdx.x * blockDim.x + threadIdx.x;
    if (i <= NN) deg[i] = 0;
}
__global__ void hist_kernel(const int* __restrict__ dst, int* __restrict__ deg) {
    int e = blockIdx.x * blockDim.x + threadIdx.x;
    if (e < NE) atomicAdd(&deg[dst[e]], 1);
}
__global__ void blockscan_kernel(const int* __restrict__ deg, int* __restrict__ off,
                                 int* __restrict__ bsums) {
    __shared__ int wsum[32];
    int i = blockIdx.x * 1024 + threadIdx.x;
    int v = (i < NN) ? deg[i] : 0;
    int lane = threadIdx.x & 31, w = threadIdx.x >> 5;
    int inc = v;
    #pragma unroll
    for (int o = 1; o < 32; o <<= 1) {
        int t = __shfl_up_sync(0xffffffffu, inc, o);
        if (lane >= o) inc += t;
    }
    if (lane == 31) wsum[w] = inc;
    __syncthreads();
    if (w == 0) {
        int s = wsum[lane];
        #pragma unroll
        for (int o = 1; o < 32; o <<= 1) {
            int t = __shfl_up_sync(0xffffffffu, s, o);
            if (lane >= o) s += t;
        }
        wsum[lane] = s;
    }
    __syncthreads();
    int prefix = (w > 0) ? wsum[w - 1] : 0;
    if (i <= NN) off[i] = prefix + inc - v;
    if (threadIdx.x == 1023) bsums[blockIdx.x] = wsum[31];
}
__global__ void scanb_kernel(int* __restrict__ bsums) {
    __shared__ int sm[64];
    int lane = threadIdx.x;
    int v = (lane < SCAN_BLOCKS) ? bsums[lane] : 0;
    sm[lane] = v;
    __syncthreads();
    for (int o = 1; o < 64; o <<= 1) {
        int t = (lane >= o) ? sm[lane - o] : 0;
        __syncthreads();
        sm[lane] += t;
        __syncthreads();
    }
    if (lane < SCAN_BLOCKS) bsums[lane] = sm[lane] - v;
}
__global__ void addoff_kernel(int* __restrict__ off, const int* __restrict__ bsums,
                              int* __restrict__ cur) {
    int i = blockIdx.x * 1024 + threadIdx.x;
    if (i <= NN) {
        int v = off[i] + bsums[blockIdx.x];
        off[i] = v;
        if (i < NN) cur[i] = v;
    }
}
__global__ void scatter_kernel(const int* __restrict__ src, const int* __restrict__ dst,
                               int* __restrict__ cur, int* __restrict__ srcs) {
    int e = blockIdx.x * blockDim.x + threadIdx.x;
    if (e < NE) {
        int p = atomicAdd(&cur[dst[e]], 1);
        srcs[p] = src[e];
    }
}

// ===================== GIN aggregate =====================
__global__ void agg_kernel(const float4* __restrict__ x, const int* __restrict__ off,
                           const int* __restrict__ srcs, float4* __restrict__ out) {
    int gw   = (blockIdx.x * blockDim.x + threadIdx.x) >> 5;
    int lane = threadIdx.x & 31;
    if (gw >= NN) return;
    int s = off[gw], e = off[gw + 1];
    float4 acc = x[gw * 32 + lane];
    #pragma unroll 2
    for (int i = s; i < e; i++) {
        int sc   = __ldg(&srcs[i]);
        float4 v = x[sc * 32 + lane];
        acc.x += v.x; acc.y += v.y; acc.z += v.z; acc.w += v.w;
    }
    out[gw * 32 + lane] = acc;
}

// ===================== weight prep: transpose + bf16 hi/lo split =====================
__global__ void prep_w_kernel(const float* __restrict__ W0, const float* __restrict__ W1,
                              const float* __restrict__ W2, const float* __restrict__ Wm1,
                              __nv_bfloat16* __restrict__ bhi, __nv_bfloat16* __restrict__ blo) {
    int idx = blockIdx.x * blockDim.x + threadIdx.x;
    if (idx >= 5 * 16384) return;
    int t = idx >> 14;
    int e = idx & 16383;
    int n = e >> 7, k = e & 127;
    float w;
    if (t == 0)      w = W0[k * 128 + n];
    else if (t == 1) w = W1[k * 128 + n];
    else if (t == 2) w = W2[k * 128 + n];
    else             w = Wm1[k * 256 + (t - 3) * 128 + n];
    __nv_bfloat16 h = __float2bfloat16(w);
    __nv_bfloat16 l = __float2bfloat16(w - __bfloat162float(h));
    bhi[idx] = h;
    blo[idx] = l;
}

// ===================== tensor-core GEMM (mma.sync bf16 hi/lo split), BM=256 =====================
// out[rows, colOff:+128] = relu(A[rows,128] @ Wt^T + b)
// CTA: 256 rows x 128 cols, K=128 resident, 512 threads (16 warps, 4x4 warp grid,
// warp tile 64x32 = 4x4 m16n8k16 tiles).
#define LDA    136                 // padded bf16 stride (272 B)
#define A_HI   0
#define A_LO   69632
#define B_HI   139264
#define B_LO   174080
#define SM_BS  208896
#define SM_BYTES (208896 + 512 + 128)

__global__ void __launch_bounds__(512, 1)
gemm_tc_kernel(const float* __restrict__ A,
               const __nv_bfloat16* __restrict__ gBhi,
               const __nv_bfloat16* __restrict__ gBlo,
               const float* __restrict__ bias,
               float* __restrict__ out,
               int tile0, int outCols) {
    extern __shared__ char smem[];
    const int tid  = threadIdx.x;
    const int wid  = tid >> 5;
    const int lane = tid & 31;
    const int t = tile0 + blockIdx.y;
    const int colOff = blockIdx.y * 128;
    const int rowBase = blockIdx.x * 256;

    // ---- load A tile (256x128 fp32 -> bf16 hi/lo, padded smem) ----
    {
        const float4* A4 = reinterpret_cast<const float4*>(A);
        #pragma unroll
        for (int i = 0; i < 16; i++) {
            int lin = tid + i * 512;          // 8192 float4
            int r   = lin >> 5;
            int c4  = lin & 31;
            int gr  = rowBase + r;
            float4 f = (gr < NN) ? A4[gr * 32 + c4] : make_float4(0.f, 0.f, 0.f, 0.f);
            __nv_bfloat162 h0 = __floats2bfloat162_rn(f.x, f.y);
            __nv_bfloat162 h1 = __floats2bfloat162_rn(f.z, f.w);
            float2 hf0 = __bfloat1622float2(h0);
            float2 hf1 = __bfloat1622float2(h1);
            __nv_bfloat162 l0 = __floats2bfloat162_rn(f.x - hf0.x, f.y - hf0.y);
            __nv_bfloat162 l1 = __floats2bfloat162_rn(f.z - hf1.x, f.w - hf1.y);
            uint2 hv = make_uint2(reinterpret_cast<uint32_t&>(h0), reinterpret_cast<uint32_t&>(h1));
            uint2 lv = make_uint2(reinterpret_cast<uint32_t&>(l0), reinterpret_cast<uint32_t&>(l1));
            int boff = r * (LDA * 2) + c4 * 8;
            *reinterpret_cast<uint2*>(smem + A_HI + boff) = hv;
            *reinterpret_cast<uint2*>(smem + A_LO + boff) = lv;
        }
    }
    // ---- load B tiles (prepped bf16, linear copy into padded smem) ----
    {
        const uint4* shi = reinterpret_cast<const uint4*>(gBhi + t * 16384);
        const uint4* slo = reinterpret_cast<const uint4*>(gBlo + t * 16384);
        #pragma unroll
        for (int i = 0; i < 4; i++) {
            int lin = tid + i * 512;          // 2048 uint4
            int n = lin >> 4, q = lin & 15;
            int boff = n * (LDA * 2) + q * 16;
            *reinterpret_cast<uint4*>(smem + B_HI + boff) = shi[lin];
            *reinterpret_cast<uint4*>(smem + B_LO + boff) = slo[lin];
        }
        if (tid < 128) reinterpret_cast<float*>(smem + SM_BS)[tid] = bias[colOff + tid];
    }
    __syncthreads();

    // ---- warp MMA mainloop: 16 warps, warp tile 64x32 ----
    const int wm = (wid & 3) * 64;
    const int wn = (wid >> 2) * 32;
    float acc[4][4][4];
    #pragma unroll
    for (int mt = 0; mt < 4; mt++)
        #pragma unroll
        for (int nt = 0; nt < 4; nt++)
            #pragma unroll
            for (int j = 0; j < 4; j++) acc[mt][nt][j] = 0.f;

    const uint32_t sb = smem_u32(smem);
    const uint32_t aBaseHi = sb + A_HI + (wm + (lane & 15)) * (LDA * 2) + (lane >> 4) * 16;
    const uint32_t aBaseLo = aBaseHi + (A_LO - A_HI);
    const uint32_t bBaseHi = sb + B_HI + (wn + (lane & 7)) * (LDA * 2) + ((lane >> 3) & 1) * 16;
    const uint32_t bBaseLo = bBaseHi + (B_LO - B_HI);

    #pragma unroll
    for (int ks = 0; ks < 8; ks++) {
        uint32_t bh[4][2], bl[4][2];
        #pragma unroll
        for (int nt = 0; nt < 4; nt++) {
            ldsm_x2(bh[nt], bBaseHi + nt * 8 * (LDA * 2) + ks * 32);
            ldsm_x2(bl[nt], bBaseLo + nt * 8 * (LDA * 2) + ks * 32);
        }
        #pragma unroll
        for (int mt = 0; mt < 4; mt++) {
            uint32_t ah[4], al[4];
            ldsm_x4(ah, aBaseHi + mt * 16 * (LDA * 2) + ks * 32);
            ldsm_x4(al, aBaseLo + mt * 16 * (LDA * 2) + ks * 32);
            #pragma unroll
            for (int nt = 0; nt < 4; nt++) {
                mma_bf16(acc[mt][nt], ah, bh[nt]);
                mma_bf16(acc[mt][nt], ah, bl[nt]);
                mma_bf16(acc[mt][nt], al, bh[nt]);
            }
        }
    }

    // ---- epilogue: bias + relu, fp32 store ----
    const float* bs = reinterpret_cast<const float*>(smem + SM_BS);
    #pragma unroll
    for (int mt = 0; mt < 4; mt++) {
        #pragma unroll
        for (int nt = 0; nt < 4; nt++) {
            int lc = wn + nt * 8 + (lane & 3) * 2;
            int r0 = rowBase + wm + mt * 16 + (lane >> 2);
            float b0 = bs[lc], b1 = bs[lc + 1];
            int c = colOff + lc;
            if (r0 < NN) {
                float2 v;
                v.x = fmaxf(acc[mt][nt][0] + b0, 0.f);
                v.y = fmaxf(acc[mt][nt][1] + b1, 0.f);
                *reinterpret_cast<float2*>(out + (size_t)r0 * outCols + c) = v;
            }
            if (r0 + 8 < NN) {
                float2 v;
                v.x = fmaxf(acc[mt][nt][2] + b0, 0.f);
                v.y = fmaxf(acc[mt][nt][3] + b1, 0.f);
                *reinterpret_cast<float2*>(out + (size_t)(r0 + 8) * outCols + c) = v;
            }
        }
    }
}

// ===================== head =====================
__global__ void head_kernel(const float* __restrict__ A, const float* __restrict__ W,
                            const float* __restrict__ b, float* __restrict__ out) {
    __shared__ float Ws[256 * 10];
    __shared__ float bs[10];
    for (int i = threadIdx.x; i < 2560; i += blockDim.x) Ws[i] = W[i];
    if (threadIdx.x < 10) bs[threadIdx.x] = b[threadIdx.x];
    __syncthreads();

    int gw   = (blockIdx.x * blockDim.x + threadIdx.x) >> 5;
    int lane = threadIdx.x & 31;
    if (gw >= NN) return;

    float acc[10];
    #pragma unroll
    for (int c = 0; c < 10; c++) acc[c] = 0.f;
    for (int k = lane; k < 256; k += 32) {
        float a = A[gw * 256 + k];
        #pragma unroll
        for (int c = 0; c < 10; c++) acc[c] += a * Ws[k * 10 + c];
    }
    #pragma unroll
    for (int c = 0; c < 10; c++) {
        #pragma unroll
        for (int o = 16; o; o >>= 1) acc[c] += __shfl_down_sync(0xffffffffu, acc[c], o);
    }
    if (lane == 0) {
        #pragma unroll
        for (int c = 0; c < 10; c++) out[gw * 10 + c] = acc[c] + bs[c];
    }
}

// ===================== host =====================
extern "C" void kernel_launch(void* const* d_in, const int* in_sizes, int n_in,
                              void* d_out, int out_size) {
    const float* x   = (const float*)d_in[0];
    const int*   ei  = (const int*)d_in[1];
    const float* W0  = (const float*)d_in[2];
    const float* b0  = (const float*)d_in[3];
    const float* W1  = (const float*)d_in[4];
    const float* b1  = (const float*)d_in[5];
    const float* W2  = (const float*)d_in[6];
    const float* b2  = (const float*)d_in[7];
    const float* Wm1 = (const float*)d_in[8];
    const float* bm1 = (const float*)d_in[9];
    const float* Wm2 = (const float*)d_in[10];
    const float* bm2 = (const float*)d_in[11];
    const int* src = ei;
    const int* dst = ei + NE;

    int *deg, *off, *cur, *srcs, *bsums;
    float *bufA, *bufB;
    __nv_bfloat16 *bhi, *blo;
    cudaGetSymbolAddress((void**)&deg,   g_deg);
    cudaGetSymbolAddress((void**)&off,   g_off);
    cudaGetSymbolAddress((void**)&cur,   g_cur);
    cudaGetSymbolAddress((void**)&srcs,  g_srcs);
    cudaGetSymbolAddress((void**)&bsums, g_bsums);
    cudaGetSymbolAddress((void**)&bufA,  g_bufA);
    cudaGetSymbolAddress((void**)&bufB,  g_bufB);
    cudaGetSymbolAddress((void**)&bhi,   g_Bhi);
    cudaGetSymbolAddress((void**)&blo,   g_Blo);

    cudaFuncSetAttribute(gemm_tc_kernel,
                         cudaFuncAttributeMaxDynamicSharedMemorySize, SM_BYTES);

    // weight prep + CSR build
    prep_w_kernel<<<(5 * 16384 + 255) / 256, 256>>>(W0, W1, W2, Wm1, bhi, blo);
    zero_kernel<<<(NN + 1 + 255) / 256, 256>>>(deg);
    hist_kernel<<<(NE + 255) / 256, 256>>>(dst, deg);
    blockscan_kernel<<<SCAN_BLOCKS, 1024>>>(deg, off, bsums);
    scanb_kernel<<<1, 64>>>(bsums);
    addoff_kernel<<<SCAN_BLOCKS, 1024>>>(off, bsums, cur);
    scatter_kernel<<<(NE + 255) / 256, 256>>>(src, dst, cur, srcs);

    const int warpBlocks = (NN * 32 + 255) / 256;
    const int gemmBlocks = (NN + 255) / 256;   // 196

    // layer 0
    agg_kernel<<<warpBlocks, 256>>>((const float4*)x, off, srcs, (float4*)bufA);
    gemm_tc_kernel<<<dim3(gemmBlocks, 1), 512, SM_BYTES>>>(bufA, bhi, blo, b0, bufB, 0, 128);
    // layer 1
    agg_kernel<<<warpBlocks, 256>>>((const float4*)bufB, off, srcs, (float4*)bufA);
    gemm_tc_kernel<<<dim3(gemmBlocks, 1), 512, SM_BYTES>>>(bufA, bhi, blo, b1, bufB, 1, 128);
    // layer 2
    agg_kernel<<<warpBlocks, 256>>>((const float4*)bufB, off, srcs, (float4*)bufA);
    gemm_tc_kernel<<<dim3(gemmBlocks, 1), 512, SM_BYTES>>>(bufA, bhi, blo, b2, bufB, 2, 128);
    // MLP hidden [N,256] as two 128-col tiles
    gemm_tc_kernel<<<dim3(gemmBlocks, 2), 512, SM_BYTES>>>(bufB, bhi, blo, bm1, bufA, 3, 256);
    // head
    head_kernel<<<warpBlocks, 256>>>(bufA, Wm2, bm2, (float*)d_out);
}

// round 14
// speedup vs baseline: 1.1110x; 1.0497x over previous
#include <cuda_runtime.h>
#include <cuda_bf16.h>
#include <stdint.h>

#define NN 50000
#define NE 600000
#define SCAN_BLOCKS ((NN + 1 + 1023) / 1024)   // 49

// ---- static device scratch ----
__device__ int   g_deg[NN + 1];
__device__ int   g_off[NN + 1];
__device__ int   g_cur[NN];
__device__ int   g_srcs[NE];
__device__ int   g_bsums[64];
__device__ float g_bufA[NN * 256];
__device__ float g_bufB[NN * 128];
// 5 prepped weight tiles (W0,W1,W2, Wm1[:,0:128], Wm1[:,128:256]) transposed to
// Wt[n][k] row-major bf16 (hi and lo split), 128x128 each
__device__ __nv_bfloat16 g_Bhi[5 * 16384];
__device__ __nv_bfloat16 g_Blo[5 * 16384];

// ===================== warp MMA helpers (base-target safe: sm_80+) =====================
__device__ __forceinline__ uint32_t smem_u32(const void* p) {
    uint32_t a;
    asm("{ .reg .u64 t; cvta.to.shared.u64 t, %1; cvt.u32.u64 %0, t; }" : "=r"(a) : "l"(p));
    return a;
}
__device__ __forceinline__ void ldsm_x4(uint32_t* a, uint32_t addr) {
    asm volatile("ldmatrix.sync.aligned.m8n8.x4.shared.b16 {%0,%1,%2,%3}, [%4];"
                 : "=r"(a[0]), "=r"(a[1]), "=r"(a[2]), "=r"(a[3]) : "r"(addr));
}
__device__ __forceinline__ void ldsm_x2(uint32_t* b, uint32_t addr) {
    asm volatile("ldmatrix.sync.aligned.m8n8.x2.shared.b16 {%0,%1}, [%2];"
                 : "=r"(b[0]), "=r"(b[1]) : "r"(addr));
}
__device__ __forceinline__ void mma_bf16(float* c, const uint32_t* a, const uint32_t* b) {
    asm volatile("mma.sync.aligned.m16n8k16.row.col.f32.bf16.bf16.f32 "
                 "{%0,%1,%2,%3}, {%4,%5,%6,%7}, {%8,%9}, {%0,%1,%2,%3};"
                 : "+f"(c[0]), "+f"(c[1]), "+f"(c[2]), "+f"(c[3])
                 : "r"(a[0]), "r"(a[1]), "r"(a[2]), "r"(a[3]), "r"(b[0]), "r"(b[1]));
}

// ===================== CSR build =====================
__global__ void zero_kernel(int* __restrict__ deg) {
    int i = blockIdx.x * blockDim.x + threadIdx.x;
    if (i <= NN) deg[i] = 0;
}
__global__ void hist_kernel(const int* __restrict__ dst, int* __restrict__ deg) {
    int e = blockIdx.x * blockDim.x + threadIdx.x;
    if (e < NE) atomicAdd(&deg[dst[e]], 1);
}
__global__ void blockscan_kernel(const int* __restrict__ deg, int* __restrict__ off,
                                 int* __restrict__ bsums) {
    __shared__ int wsum[32];
    int i = blockIdx.x * 1024 + threadIdx.x;
    int v = (i < NN) ? deg[i] : 0;
    int lane = threadIdx.x & 31, w = threadIdx.x >> 5;
    int inc = v;
    #pragma unroll
    for (int o = 1; o < 32; o <<= 1) {
        int t = __shfl_up_sync(0xffffffffu, inc, o);
        if (lane >= o) inc += t;
    }
    if (lane == 31) wsum[w] = inc;
    __syncthreads();
    if (w == 0) {
        int s = wsum[lane];
        #pragma unroll
        for (int o = 1; o < 32; o <<= 1) {
            int t = __shfl_up_sync(0xffffffffu, s, o);
            if (lane >= o) s += t;
        }
        wsum[lane] = s;
    }
    __syncthreads();
    int prefix = (w > 0) ? wsum[w - 1] : 0;
    if (i <= NN) off[i] = prefix + inc - v;
    if (threadIdx.x == 1023) bsums[blockIdx.x] = wsum[31];
}
__global__ void scanb_kernel(int* __restrict__ bsums) {
    __shared__ int sm[64];
    int lane = threadIdx.x;
    int v = (lane < SCAN_BLOCKS) ? bsums[lane] : 0;
    sm[lane] = v;
    __syncthreads();
    for (int o = 1; o < 64; o <<= 1) {
        int t = (lane >= o) ? sm[lane - o] : 0;
        __syncthreads();
        sm[lane] += t;
        __syncthreads();
    }
    if (lane < SCAN_BLOCKS) bsums[lane] = sm[lane] - v;
}
__global__ void addoff_kernel(int* __restrict__ off, const int* __restrict__ bsums,
                              int* __restrict__ cur) {
    int i = blockIdx.x * 1024 + threadIdx.x;
    if (i <= NN) {
        int v = off[i] + bsums[blockIdx.x];
        off[i] = v;
        if (i < NN) cur[i] = v;
    }
}
__global__ void scatter_kernel(const int* __restrict__ src, const int* __restrict__ dst,
                               int* __restrict__ cur, int* __restrict__ srcs) {
    int e = blockIdx.x * blockDim.x + threadIdx.x;
    if (e < NE) {
        int p = atomicAdd(&cur[dst[e]], 1);
        srcs[p] = src[e];
    }
}

// ===================== GIN aggregate =====================
__global__ void agg_kernel(const float4* __restrict__ x, const int* __restrict__ off,
                           const int* __restrict__ srcs, float4* __restrict__ out) {
    int gw   = (blockIdx.x * blockDim.x + threadIdx.x) >> 5;
    int lane = threadIdx.x & 31;
    if (gw >= NN) return;
    int s = off[gw], e = off[gw + 1];
    float4 acc = x[gw * 32 + lane];
    #pragma unroll 2
    for (int i = s; i < e; i++) {
        int sc   = __ldg(&srcs[i]);
        float4 v = x[sc * 32 + lane];
        acc.x += v.x; acc.y += v.y; acc.z += v.z; acc.w += v.w;
    }
    out[gw * 32 + lane] = acc;
}

// ===================== weight prep: transpose + bf16 hi/lo split =====================
__global__ void prep_w_kernel(const float* __restrict__ W0, const float* __restrict__ W1,
                              const float* __restrict__ W2, const float* __restrict__ Wm1,
                              __nv_bfloat16* __restrict__ bhi, __nv_bfloat16* __restrict__ blo) {
    int idx = blockIdx.x * blockDim.x + threadIdx.x;
    if (idx >= 5 * 16384) return;
    int t = idx >> 14;
    int e = idx & 16383;
    int n = e >> 7, k = e & 127;
    float w;
    if (t == 0)      w = W0[k * 128 + n];
    else if (t == 1) w = W1[k * 128 + n];
    else if (t == 2) w = W2[k * 128 + n];
    else             w = Wm1[k * 256 + (t - 3) * 128 + n];
    __nv_bfloat16 h = __float2bfloat16(w);
    __nv_bfloat16 l = __float2bfloat16(w - __bfloat162float(h));
    bhi[idx] = h;
    blo[idx] = l;
}

// ===================== tensor-core GEMM (mma.sync bf16 hi/lo split) =====================
// out[rows, 0:128*nBTiles] = relu(A[rows,128] @ Wt^T + b)
// CTA: 128 rows, K=128 resident, 256 threads (8 warps, 2x4 warp grid, warp tile 64x32).
// nBTiles = 1 or 2 column tiles of 128, both resident in smem; A loaded/converted ONCE.
#define LDA      136               // padded bf16 stride (272 B)
#define A_HI     0
#define A_LO     34816
#define B_HI     69632             // up to 2 tiles x 34816
#define B_LO     139264
#define SM_BS    208896            // up to 256 floats
#define SM_BYTES (208896 + 1024 + 128)

__global__ void __launch_bounds__(256, 1)
gemm_tc_kernel(const float* __restrict__ A,
               const __nv_bfloat16* __restrict__ gBhi,
               const __nv_bfloat16* __restrict__ gBlo,
               const float* __restrict__ bias,
               float* __restrict__ out,
               int tile0, int outCols, int nBTiles) {
    extern __shared__ char smem[];
    const int tid  = threadIdx.x;
    const int wid  = tid >> 5;
    const int lane = tid & 31;
    const int rowBase = blockIdx.x * 128;

    // ---- load A tile (128x128 fp32 -> bf16 hi/lo, padded smem) ----
    {
        const float4* A4 = reinterpret_cast<const float4*>(A);
        #pragma unroll
        for (int i = 0; i < 16; i++) {
            int lin = tid + i * 256;          // 4096 float4
            int r   = lin >> 5;
            int c4  = lin & 31;
            int gr  = rowBase + r;
            float4 f = (gr < NN) ? A4[gr * 32 + c4] : make_float4(0.f, 0.f, 0.f, 0.f);
            __nv_bfloat162 h0 = __floats2bfloat162_rn(f.x, f.y);
            __nv_bfloat162 h1 = __floats2bfloat162_rn(f.z, f.w);
            float2 hf0 = __bfloat1622float2(h0);
            float2 hf1 = __bfloat1622float2(h1);
            __nv_bfloat162 l0 = __floats2bfloat162_rn(f.x - hf0.x, f.y - hf0.y);
            __nv_bfloat162 l1 = __floats2bfloat162_rn(f.z - hf1.x, f.w - hf1.y);
            uint2 hv = make_uint2(reinterpret_cast<uint32_t&>(h0), reinterpret_cast<uint32_t&>(h1));
            uint2 lv = make_uint2(reinterpret_cast<uint32_t&>(l0), reinterpret_cast<uint32_t&>(l1));
            int boff = r * (LDA * 2) + c4 * 8;
            *reinterpret_cast<uint2*>(smem + A_HI + boff) = hv;
            *reinterpret_cast<uint2*>(smem + A_LO + boff) = lv;
        }
    }
    // ---- load B tiles (prepped bf16, linear copy into padded smem) ----
    for (int bt = 0; bt < nBTiles; bt++) {
        const uint4* shi = reinterpret_cast<const uint4*>(gBhi + (tile0 + bt) * 16384);
        const uint4* slo = reinterpret_cast<const uint4*>(gBlo + (tile0 + bt) * 16384);
        const int dstOff = bt * 34816;
        #pragma unroll
        for (int i = 0; i < 8; i++) {
            int lin = tid + i * 256;          // 2048 uint4
            int n = lin >> 4, q = lin & 15;
            int boff = n * (LDA * 2) + q * 16;
            *reinterpret_cast<uint4*>(smem + B_HI + dstOff + boff) = shi[lin];
            *reinterpret_cast<uint4*>(smem + B_LO + dstOff + boff) = slo[lin];
        }
    }
    for (int i = tid; i < 128 * nBTiles; i += 256)
        reinterpret_cast<float*>(smem + SM_BS)[i] = bias[i];
    __syncthreads();

    // ---- per column-tile: mainloop + epilogue (A reused from smem) ----
    const int wm = (wid & 1) * 64;
    const int wn = (wid >> 1) * 32;
    const uint32_t sb = smem_u32(smem);
    const uint32_t aBaseHi = sb + A_HI + (wm + (lane & 15)) * (LDA * 2) + (lane >> 4) * 16;
    const uint32_t aBaseLo = aBaseHi + (A_LO - A_HI);
    const float* bs = reinterpret_cast<const float*>(smem + SM_BS);

    for (int bt = 0; bt < nBTiles; bt++) {
        float acc[4][4][4];
        #pragma unroll
        for (int mt = 0; mt < 4; mt++)
            #pragma unroll
            for (int nt = 0; nt < 4; nt++)
                #pragma unroll
                for (int j = 0; j < 4; j++) acc[mt][nt][j] = 0.f;

        const uint32_t bBaseHi = sb + B_HI + bt * 34816
                               + (wn + (lane & 7)) * (LDA * 2) + ((lane >> 3) & 1) * 16;
        const uint32_t bBaseLo = bBaseHi + (B_LO - B_HI);

        #pragma unroll
        for (int ks = 0; ks < 8; ks++) {
            uint32_t bh[4][2], bl[4][2];
            #pragma unroll
            for (int nt = 0; nt < 4; nt++) {
                ldsm_x2(bh[nt], bBaseHi + nt * 8 * (LDA * 2) + ks * 32);
                ldsm_x2(bl[nt], bBaseLo + nt * 8 * (LDA * 2) + ks * 32);
            }
            #pragma unroll
            for (int mt = 0; mt < 4; mt++) {
                uint32_t ah[4], al[4];
                ldsm_x4(ah, aBaseHi + mt * 16 * (LDA * 2) + ks * 32);
                ldsm_x4(al, aBaseLo + mt * 16 * (LDA * 2) + ks * 32);
                #pragma unroll
                for (int nt = 0; nt < 4; nt++) {
                    mma_bf16(acc[mt][nt], ah, bh[nt]);
                    mma_bf16(acc[mt][nt], ah, bl[nt]);
                    mma_bf16(acc[mt][nt], al, bh[nt]);
                }
            }
        }

        const int colOff = bt * 128;
        #pragma unroll
        for (int mt = 0; mt < 4; mt++) {
            #pragma unroll
            for (int nt = 0; nt < 4; nt++) {
                int lc = wn + nt * 8 + (lane & 3) * 2;
                int r0 = rowBase + wm + mt * 16 + (lane >> 2);
                float b0 = bs[colOff + lc], b1 = bs[colOff + lc + 1];
                int c = colOff + lc;
                if (r0 < NN) {
                    float2 v;
                    v.x = fmaxf(acc[mt][nt][0] + b0, 0.f);
                    v.y = fmaxf(acc[mt][nt][1] + b1, 0.f);
                    *reinterpret_cast<float2*>(out + (size_t)r0 * outCols + c) = v;
                }
                if (r0 + 8 < NN) {
                    float2 v;
                    v.x = fmaxf(acc[mt][nt][2] + b0, 0.f);
                    v.y = fmaxf(acc[mt][nt][3] + b1, 0.f);
                    *reinterpret_cast<float2*>(out + (size_t)(r0 + 8) * outCols + c) = v;
                }
            }
        }
    }
}

// ===================== head =====================
__global__ void head_kernel(const float* __restrict__ A, const float* __restrict__ W,
                            const float* __restrict__ b, float* __restrict__ out) {
    __shared__ float Ws[256 * 10];
    __shared__ float bs[10];
    for (int i = threadIdx.x; i < 2560; i += blockDim.x) Ws[i] = W[i];
    if (threadIdx.x < 10) bs[threadIdx.x] = b[threadIdx.x];
    __syncthreads();

    int gw   = (blockIdx.x * blockDim.x + threadIdx.x) >> 5;
    int lane = threadIdx.x & 31;
    if (gw >= NN) return;

    float acc[10];
    #pragma unroll
    for (int c = 0; c < 10; c++) acc[c] = 0.f;
    for (int k = lane; k < 256; k += 32) {
        float a = A[gw * 256 + k];
        #pragma unroll
        for (int c = 0; c < 10; c++) acc[c] += a * Ws[k * 10 + c];
    }
    #pragma unroll
    for (int c = 0; c < 10; c++) {
        #pragma unroll
        for (int o = 16; o; o >>= 1) acc[c] += __shfl_down_sync(0xffffffffu, acc[c], o);
    }
    if (lane == 0) {
        #pragma unroll
        for (int c = 0; c < 10; c++) out[gw * 10 + c] = acc[c] + bs[c];
    }
}

// ===================== host =====================
extern "C" void kernel_launch(void* const* d_in, const int* in_sizes, int n_in,
                              void* d_out, int out_size) {
    const float* x   = (const float*)d_in[0];
    const int*   ei  = (const int*)d_in[1];
    const float* W0  = (const float*)d_in[2];
    const float* b0  = (const float*)d_in[3];
    const float* W1  = (const float*)d_in[4];
    const float* b1  = (const float*)d_in[5];
    const float* W2  = (const float*)d_in[6];
    const float* b2  = (const float*)d_in[7];
    const float* Wm1 = (const float*)d_in[8];
    const float* bm1 = (const float*)d_in[9];
    const float* Wm2 = (const float*)d_in[10];
    const float* bm2 = (const float*)d_in[11];
    const int* src = ei;
    const int* dst = ei + NE;

    int *deg, *off, *cur, *srcs, *bsums;
    float *bufA, *bufB;
    __nv_bfloat16 *bhi, *blo;
    cudaGetSymbolAddress((void**)&deg,   g_deg);
    cudaGetSymbolAddress((void**)&off,   g_off);
    cudaGetSymbolAddress((void**)&cur,   g_cur);
    cudaGetSymbolAddress((void**)&srcs,  g_srcs);
    cudaGetSymbolAddress((void**)&bsums, g_bsums);
    cudaGetSymbolAddress((void**)&bufA,  g_bufA);
    cudaGetSymbolAddress((void**)&bufB,  g_bufB);
    cudaGetSymbolAddress((void**)&bhi,   g_Bhi);
    cudaGetSymbolAddress((void**)&blo,   g_Blo);

    cudaFuncSetAttribute(gemm_tc_kernel,
                         cudaFuncAttributeMaxDynamicSharedMemorySize, SM_BYTES);

    // weight prep + CSR build
    prep_w_kernel<<<(5 * 16384 + 255) / 256, 256>>>(W0, W1, W2, Wm1, bhi, blo);
    zero_kernel<<<(NN + 1 + 255) / 256, 256>>>(deg);
    hist_kernel<<<(NE + 255) / 256, 256>>>(dst, deg);
    blockscan_kernel<<<SCAN_BLOCKS, 1024>>>(deg, off, bsums);
    scanb_kernel<<<1, 64>>>(bsums);
    addoff_kernel<<<SCAN_BLOCKS, 1024>>>(off, bsums, cur);
    scatter_kernel<<<(NE + 255) / 256, 256>>>(src, dst, cur, srcs);

    const int warpBlocks = (NN * 32 + 255) / 256;
    const int gemmBlocks = (NN + 127) / 128;   // 391

    // layer 0
    agg_kernel<<<warpBlocks, 256>>>((const float4*)x, off, srcs, (float4*)bufA);
    gemm_tc_kernel<<<gemmBlocks, 256, SM_BYTES>>>(bufA, bhi, blo, b0, bufB, 0, 128, 1);
    // layer 1
    agg_kernel<<<warpBlocks, 256>>>((const float4*)bufB, off, srcs, (float4*)bufA);
    gemm_tc_kernel<<<gemmBlocks, 256, SM_BYTES>>>(bufA, bhi, blo, b1, bufB, 1, 128, 1);
    // layer 2
    agg_kernel<<<warpBlocks, 256>>>((const float4*)bufB, off, srcs, (float4*)bufA);
    gemm_tc_kernel<<<gemmBlocks, 256, SM_BYTES>>>(bufA, bhi, blo, b2, bufB, 2, 128, 1);
    // MLP hidden [N,256]: both column tiles in ONE launch (A loaded once)
    gemm_tc_kernel<<<gemmBlocks, 256, SM_BYTES>>>(bufB, bhi, blo, bm1, bufA, 3, 256, 2);
    // head
    head_kernel<<<warpBlocks, 256>>>(bufA, Wm2, bm2, (float*)d_out);
}

// round 15
// speedup vs baseline: 1.3392x; 1.2053x over previous
#include <cuda_runtime.h>
#include <cuda_bf16.h>
#include <stdint.h>

#define NN 50000
#define NE 600000
#define SCAN_BLOCKS ((NN + 1 + 1023) / 1024)   // 49

// ---- static device scratch ----
__device__ int   g_deg[NN + 1];
__device__ int   g_off[NN + 1];
__device__ int   g_cur[NN];
__device__ int   g_srcs[NE];
__device__ unsigned long long g_descs[64];
__device__ float g_bufA[NN * 128];
__device__ float g_bufB[NN * 128];
// prepped weights: tiles 0..4 = W0,W1,W2,Wm1[:,0:128],Wm1[:,128:256] as Wt[n][k] 128x128
// (hi/lo bf16 split); appended at offset 81920: Wm2t padded [16][k<=263] stride 264
#define WM2_GOFF 81920
__device__ __align__(256) __nv_bfloat16 g_Bhi[5 * 16384 + 16 * 264];
__device__ __align__(256) __nv_bfloat16 g_Blo[5 * 16384 + 16 * 264];

// ===================== warp MMA helpers (base-target safe: sm_80+) =====================
__device__ __forceinline__ uint32_t smem_u32(const void* p) {
    uint32_t a;
    asm("{ .reg .u64 t; cvta.to.shared.u64 t, %1; cvt.u32.u64 %0, t; }" : "=r"(a) : "l"(p));
    return a;
}
__device__ __forceinline__ void ldsm_x4(uint32_t* a, uint32_t addr) {
    asm volatile("ldmatrix.sync.aligned.m8n8.x4.shared.b16 {%0,%1,%2,%3}, [%4];"
                 : "=r"(a[0]), "=r"(a[1]), "=r"(a[2]), "=r"(a[3]) : "r"(addr));
}
__device__ __forceinline__ void ldsm_x2(uint32_t* b, uint32_t addr) {
    asm volatile("ldmatrix.sync.aligned.m8n8.x2.shared.b16 {%0,%1}, [%2];"
                 : "=r"(b[0]), "=r"(b[1]) : "r"(addr));
}
__device__ __forceinline__ void mma_bf16(float* c, const uint32_t* a, const uint32_t* b) {
    asm volatile("mma.sync.aligned.m16n8k16.row.col.f32.bf16.bf16.f32 "
                 "{%0,%1,%2,%3}, {%4,%5,%6,%7}, {%8,%9}, {%0,%1,%2,%3};"
                 : "+f"(c[0]), "+f"(c[1]), "+f"(c[2]), "+f"(c[3])
                 : "r"(a[0]), "r"(a[1]), "r"(a[2]), "r"(a[3]), "r"(b[0]), "r"(b[1]));
}

// ===================== CSR build =====================
__global__ void zero_kernel(int* __restrict__ deg, unsigned long long* __restrict__ descs) {
    int i = blockIdx.x * blockDim.x + threadIdx.x;
    if (i <= NN) deg[i] = 0;
    if (i < 64)  descs[i] = 0ull;
}
__global__ void hist_kernel(const int* __restrict__ dst, int* __restrict__ deg) {
    int e = blockIdx.x * blockDim.x + threadIdx.x;
    if (e < NE) atomicAdd(&deg[dst[e]], 1);
}
// single-pass exclusive scan via decoupled lookback (packed 64-bit descriptors)
__global__ void scanfused_kernel(const int* __restrict__ deg, int* __restrict__ off,
                                 int* __restrict__ cur,
                                 volatile unsigned long long* descs) {
    __shared__ int wsum[32];
    __shared__ int sPrefix;
    const int b = blockIdx.x;
    int i = b * 1024 + threadIdx.x;
    int v = (i < NN) ? deg[i] : 0;
    int lane = threadIdx.x & 31, w = threadIdx.x >> 5;
    int inc = v;
    #pragma unroll
    for (int o = 1; o < 32; o <<= 1) {
        int t = __shfl_up_sync(0xffffffffu, inc, o);
        if (lane >= o) inc += t;
    }
    if (lane == 31) wsum[w] = inc;
    __syncthreads();
    if (w == 0) {
        int s = wsum[lane];
        #pragma unroll
        for (int o = 1; o < 32; o <<= 1) {
            int t = __shfl_up_sync(0xffffffffu, s, o);
            if (lane >= o) s += t;
        }
        wsum[lane] = s;
    }
    __syncthreads();
    int prefix = (w > 0) ? wsum[w - 1] : 0;
    int blockTotal = wsum[31];
    if (threadIdx.x == 0) {
        descs[b] = (1ull << 32) | (unsigned)blockTotal;   // aggregate available
        int p = 0;
        for (int j = b - 1; j >= 0; ) {
            unsigned long long d = descs[j];
            unsigned st = (unsigned)(d >> 32);
            if (st == 0u) continue;                       // spin (all 49 blocks resident)
            p += (int)(unsigned)(d & 0xffffffffu);
            if (st == 2u) break;                          // inclusive prefix -> done
            j--;
        }
        descs[b] = (2ull << 32) | (unsigned)(p + blockTotal);
        sPrefix = p;
    }
    __syncthreads();
    if (i <= NN) {
        int o = sPrefix + prefix + inc - v;
        off[i] = o;
        if (i < NN) cur[i] = o;
    }
}
__global__ void scatter_kernel(const int* __restrict__ src, const int* __restrict__ dst,
                               int* __restrict__ cur, int* __restrict__ srcs) {
    int e = blockIdx.x * blockDim.x + threadIdx.x;
    if (e < NE) {
        int p = atomicAdd(&cur[dst[e]], 1);
        srcs[p] = src[e];
    }
}

// ===================== GIN aggregate =====================
__global__ void agg_kernel(const float4* __restrict__ x, const int* __restrict__ off,
                           const int* __restrict__ srcs, float4* __restrict__ out) {
    int gw   = (blockIdx.x * blockDim.x + threadIdx.x) >> 5;
    int lane = threadIdx.x & 31;
    if (gw >= NN) return;
    int s = off[gw], e = off[gw + 1];
    float4 acc = x[gw * 32 + lane];
    #pragma unroll 2
    for (int i = s; i < e; i++) {
        int sc   = __ldg(&srcs[i]);
        float4 v = x[sc * 32 + lane];
        acc.x += v.x; acc.y += v.y; acc.z += v.z; acc.w += v.w;
    }
    out[gw * 32 + lane] = acc;
}

// ===================== weight prep: transpose + bf16 hi/lo split =====================
#define PREP_TOTAL (5 * 16384 + 16 * 264)
__global__ void prep_w_kernel(const float* __restrict__ W0, const float* __restrict__ W1,
                              const float* __restrict__ W2, const float* __restrict__ Wm1,
                              const float* __restrict__ Wm2,
                              __nv_bfloat16* __restrict__ bhi, __nv_bfloat16* __restrict__ blo) {
    int idx = blockIdx.x * blockDim.x + threadIdx.x;
    if (idx >= PREP_TOTAL) return;
    float w;
    if (idx < 5 * 16384) {
        int t = idx >> 14;
        int e = idx & 16383;
        int n = e >> 7, k = e & 127;
        if (t == 0)      w = W0[k * 128 + n];
        else if (t == 1) w = W1[k * 128 + n];
        else if (t == 2) w = W2[k * 128 + n];
        else             w = Wm1[k * 256 + (t - 3) * 128 + n];
    } else {
        int e = idx - 5 * 16384;
        int n = e / 264, k = e % 264;
        w = (n < 10 && k < 256) ? Wm2[k * 10 + n] : 0.f;
    }
    __nv_bfloat16 h = __float2bfloat16(w);
    __nv_bfloat16 l = __float2bfloat16(w - __bfloat162float(h));
    bhi[idx] = h;
    blo[idx] = l;
}

// ===================== tensor-core GEMM (mma.sync bf16 hi/lo split) =====================
// !doHead: out[rows, 0:128*nBTiles] = relu(A@Wt^T + b), written to global.
// doHead (Wm1+head): h tiles kept in smem (bf16 hi/lo in freed B regions), then
// logits[rows,10] = h @ Wm2 + bm2 via a short K=256 mma phase.
#define LDA      136               // padded bf16 stride (272 B)
#define A_HI     0
#define A_LO     34816
#define B_HI     69632             // bt0 hi (bt1 hi at +34816)
#define B_LO     139264            // bt0 lo (bt1 lo at +34816)
#define SM_BS    208896            // 256 bias floats
#define WM2_HI   209920            // 16 x 264 bf16 = 8448 B
#define WM2_LO   218368
#define SM_BYTES 226816

__global__ void __launch_bounds__(256, 1)
gemm_tc_kernel(const float* __restrict__ A,
               const __nv_bfloat16* __restrict__ gBhi,
               const __nv_bfloat16* __restrict__ gBlo,
               const float* __restrict__ bias,
               float* __restrict__ out,
               int tile0, int outCols, int nBTiles,
               int doHead, float* __restrict__ logits, const float* __restrict__ bm2) {
    extern __shared__ char smem[];
    const int tid  = threadIdx.x;
    const int wid  = tid >> 5;
    const int lane = tid & 31;
    const int rowBase = blockIdx.x * 128;

    // ---- load A tile (128x128 fp32 -> bf16 hi/lo, padded smem) ----
    {
        const float4* A4 = reinterpret_cast<const float4*>(A);
        #pragma unroll
        for (int i = 0; i < 16; i++) {
            int lin = tid + i * 256;          // 4096 float4
            int r   = lin >> 5;
            int c4  = lin & 31;
            int gr  = rowBase + r;
            float4 f = (gr < NN) ? A4[gr * 32 + c4] : make_float4(0.f, 0.f, 0.f, 0.f);
            __nv_bfloat162 h0 = __floats2bfloat162_rn(f.x, f.y);
            __nv_bfloat162 h1 = __floats2bfloat162_rn(f.z, f.w);
            float2 hf0 = __bfloat1622float2(h0);
            float2 hf1 = __bfloat1622float2(h1);
            __nv_bfloat162 l0 = __floats2bfloat162_rn(f.x - hf0.x, f.y - hf0.y);
            __nv_bfloat162 l1 = __floats2bfloat162_rn(f.z - hf1.x, f.w - hf1.y);
            uint2 hv = make_uint2(reinterpret_cast<uint32_t&>(h0), reinterpret_cast<uint32_t&>(h1));
            uint2 lv = make_uint2(reinterpret_cast<uint32_t&>(l0), reinterpret_cast<uint32_t&>(l1));
            int boff = r * (LDA * 2) + c4 * 8;
            *reinterpret_cast<uint2*>(smem + A_HI + boff) = hv;
            *reinterpret_cast<uint2*>(smem + A_LO + boff) = lv;
        }
    }
    // ---- load B tiles ----
    for (int bt = 0; bt < nBTiles; bt++) {
        const uint4* shi = reinterpret_cast<const uint4*>(gBhi + (tile0 + bt) * 16384);
        const uint4* slo = reinterpret_cast<const uint4*>(gBlo + (tile0 + bt) * 16384);
        const int dstOff = bt * 34816;
        #pragma unroll
        for (int i = 0; i < 8; i++) {
            int lin = tid + i * 256;          // 2048 uint4
            int n = lin >> 4, q = lin & 15;
            int boff = n * (LDA * 2) + q * 16;
            *reinterpret_cast<uint4*>(smem + B_HI + dstOff + boff) = shi[lin];
            *reinterpret_cast<uint4*>(smem + B_LO + dstOff + boff) = slo[lin];
        }
    }
    for (int i = tid; i < 128 * nBTiles; i += 256)
        reinterpret_cast<float*>(smem + SM_BS)[i] = bias[i];
    if (doHead) {
        const uint4* shiW = reinterpret_cast<const uint4*>(gBhi + WM2_GOFF);
        const uint4* sloW = reinterpret_cast<const uint4*>(gBlo + WM2_GOFF);
        for (int i = tid; i < 528; i += 256) {          // 16*264 bf16 = 528 uint4
            reinterpret_cast<uint4*>(smem + WM2_HI)[i] = shiW[i];
            reinterpret_cast<uint4*>(smem + WM2_LO)[i] = sloW[i];
        }
    }
    __syncthreads();

    const int wm = (wid & 1) * 64;
    const int wn = (wid >> 1) * 32;
    const uint32_t sb = smem_u32(smem);
    const uint32_t aBaseHi = sb + A_HI + (wm + (lane & 15)) * (LDA * 2) + (lane >> 4) * 16;
    const uint32_t aBaseLo = aBaseHi + (A_LO - A_HI);
    const float* bs = reinterpret_cast<const float*>(smem + SM_BS);

    for (int bt = 0; bt < nBTiles; bt++) {
        float acc[4][4][4];
        #pragma unroll
        for (int mt = 0; mt < 4; mt++)
            #pragma unroll
            for (int nt = 0; nt < 4; nt++)
                #pragma unroll
                for (int j = 0; j < 4; j++) acc[mt][nt][j] = 0.f;

        const uint32_t bBaseHi = sb + B_HI + bt * 34816
                               + (wn + (lane & 7)) * (LDA * 2) + ((lane >> 3) & 1) * 16;
        const uint32_t bBaseLo = bBaseHi + (B_LO - B_HI);

        #pragma unroll
        for (int ks = 0; ks < 8; ks++) {
            uint32_t bh[4][2], bl[4][2];
            #pragma unroll
            for (int nt = 0; nt < 4; nt++) {
                ldsm_x2(bh[nt], bBaseHi + nt * 8 * (LDA * 2) + ks * 32);
                ldsm_x2(bl[nt], bBaseLo + nt * 8 * (LDA * 2) + ks * 32);
            }
            #pragma unroll
            for (int mt = 0; mt < 4; mt++) {
                uint32_t ah[4], al[4];
                ldsm_x4(ah, aBaseHi + mt * 16 * (LDA * 2) + ks * 32);
                ldsm_x4(al, aBaseLo + mt * 16 * (LDA * 2) + ks * 32);
                #pragma unroll
                for (int nt = 0; nt < 4; nt++) {
                    mma_bf16(acc[mt][nt], ah, bh[nt]);
                    mma_bf16(acc[mt][nt], ah, bl[nt]);
                    mma_bf16(acc[mt][nt], al, bh[nt]);
                }
            }
        }

        if (!doHead) {
            const int colOff = bt * 128;
            #pragma unroll
            for (int mt = 0; mt < 4; mt++) {
                #pragma unroll
                for (int nt = 0; nt < 4; nt++) {
                    int lc = wn + nt * 8 + (lane & 3) * 2;
                    int r0 = rowBase + wm + mt * 16 + (lane >> 2);
                    float b0 = bs[colOff + lc], b1 = bs[colOff + lc + 1];
                    int c = colOff + lc;
                    if (r0 < NN) {
                        float2 v;
                        v.x = fmaxf(acc[mt][nt][0] + b0, 0.f);
                        v.y = fmaxf(acc[mt][nt][1] + b1, 0.f);
                        *reinterpret_cast<float2*>(out + (size_t)r0 * outCols + c) = v;
                    }
                    if (r0 + 8 < NN) {
                        float2 v;
                        v.x = fmaxf(acc[mt][nt][2] + b0, 0.f);
                        v.y = fmaxf(acc[mt][nt][3] + b1, 0.f);
                        *reinterpret_cast<float2*>(out + (size_t)(r0 + 8) * outCols + c) = v;
                    }
                }
            }
        } else {
            // all warps must finish reading this bt's B tile before we overwrite it with h
            __syncthreads();
            const int hHi = bt ? (B_HI + 34816) : B_HI;
            const int hLo = bt ? (B_LO + 34816) : B_LO;
            const int colOff = bt * 128;
            #pragma unroll
            for (int mt = 0; mt < 4; mt++) {
                #pragma unroll
                for (int nt = 0; nt < 4; nt++) {
                    int lc = wn + nt * 8 + (lane & 3) * 2;
                    int lr = wm + mt * 16 + (lane >> 2);
                    float b0 = bs[colOff + lc], b1 = bs[colOff + lc + 1];
                    {
                        float vx = fmaxf(acc[mt][nt][0] + b0, 0.f);
                        float vy = fmaxf(acc[mt][nt][1] + b1, 0.f);
                        __nv_bfloat162 h2 = __floats2bfloat162_rn(vx, vy);
                        float2 hf = __bfloat1622float2(h2);
                        __nv_bfloat162 l2 = __floats2bfloat162_rn(vx - hf.x, vy - hf.y);
                        *reinterpret_cast<uint32_t*>(smem + hHi + lr * (LDA * 2) + lc * 2) =
                            reinterpret_cast<uint32_t&>(h2);
                        *reinterpret_cast<uint32_t*>(smem + hLo + lr * (LDA * 2) + lc * 2) =
                            reinterpret_cast<uint32_t&>(l2);
                    }
                    {
                        float vx = fmaxf(acc[mt][nt][2] + b0, 0.f);
                        float vy = fmaxf(acc[mt][nt][3] + b1, 0.f);
                        __nv_bfloat162 h2 = __floats2bfloat162_rn(vx, vy);
                        float2 hf = __bfloat1622float2(h2);
                        __nv_bfloat162 l2 = __floats2bfloat162_rn(vx - hf.x, vy - hf.y);
                        *reinterpret_cast<uint32_t*>(smem + hHi + (lr + 8) * (LDA * 2) + lc * 2) =
                            reinterpret_cast<uint32_t&>(h2);
                        *reinterpret_cast<uint32_t*>(smem + hLo + (lr + 8) * (LDA * 2) + lc * 2) =
                            reinterpret_cast<uint32_t&>(l2);
                    }
                }
            }
        }
    }

    if (doHead) {
        __syncthreads();   // all h tiles written
        // head: logits[128,10] = h[128,256] @ Wm2t^T(16 padded) ; warp owns 16 rows
        const int slab = wid * 16;
        float acc2[2][4];
        #pragma unroll
        for (int nt = 0; nt < 2; nt++)
            #pragma unroll
            for (int j = 0; j < 4; j++) acc2[nt][j] = 0.f;

        const uint32_t aRowOff = (slab + (lane & 15)) * (LDA * 2) + (lane >> 4) * 16;
        const uint32_t bRowOff = (lane & 7) * 528 + ((lane >> 3) & 1) * 16;
        #pragma unroll
        for (int ks = 0; ks < 16; ks++) {
            const int half = ks >> 3, kl = ks & 7;
            uint32_t ah[4], al[4];
            ldsm_x4(ah, sb + (half ? B_HI + 34816 : B_HI) + aRowOff + kl * 32);
            ldsm_x4(al, sb + (half ? B_LO + 34816 : B_LO) + aRowOff + kl * 32);
            #pragma unroll
            for (int nt = 0; nt < 2; nt++) {
                uint32_t bh[2], bl[2];
                ldsm_x2(bh, sb + WM2_HI + bRowOff + nt * 8 * 528 + ks * 32);
                ldsm_x2(bl, sb + WM2_LO + bRowOff + nt * 8 * 528 + ks * 32);
                mma_bf16(acc2[nt], ah, bh);
                mma_bf16(acc2[nt], ah, bl);
                mma_bf16(acc2[nt], al, bh);
            }
        }
        #pragma unroll
        for (int nt = 0; nt < 2; nt++) {
            int c = nt * 8 + (lane & 3) * 2;
            if (c < 10) {
                float ba = bm2[c], bb = bm2[c + 1];
                int r0 = rowBase + slab + (lane >> 2);
                if (r0 < NN) {
                    float2 v; v.x = acc2[nt][0] + ba; v.y = acc2[nt][1] + bb;
                    *reinterpret_cast<float2*>(logits + (size_t)r0 * 10 + c) = v;
                }
                int r1 = r0 + 8;
                if (r1 < NN) {
                    float2 v; v.x = acc2[nt][2] + ba; v.y = acc2[nt][3] + bb;
                    *reinterpret_cast<float2*>(logits + (size_t)r1 * 10 + c) = v;
                }
            }
        }
    }
}

// ===================== host =====================
extern "C" void kernel_launch(void* const* d_in, const int* in_sizes, int n_in,
                              void* d_out, int out_size) {
    const float* x   = (const float*)d_in[0];
    const int*   ei  = (const int*)d_in[1];
    const float* W0  = (const float*)d_in[2];
    const float* b0  = (const float*)d_in[3];
    const float* W1  = (const float*)d_in[4];
    const float* b1  = (const float*)d_in[5];
    const float* W2  = (const float*)d_in[6];
    const float* b2  = (const float*)d_in[7];
    const float* Wm1 = (const float*)d_in[8];
    const float* bm1 = (const float*)d_in[9];
    const float* Wm2 = (const float*)d_in[10];
    const float* bm2 = (const float*)d_in[11];
    const int* src = ei;
    const int* dst = ei + NE;

    int *deg, *off, *cur, *srcs;
    unsigned long long* descs;
    float *bufA, *bufB;
    __nv_bfloat16 *bhi, *blo;
    cudaGetSymbolAddress((void**)&deg,   g_deg);
    cudaGetSymbolAddress((void**)&off,   g_off);
    cudaGetSymbolAddress((void**)&cur,   g_cur);
    cudaGetSymbolAddress((void**)&srcs,  g_srcs);
    cudaGetSymbolAddress((void**)&descs, g_descs);
    cudaGetSymbolAddress((void**)&bufA,  g_bufA);
    cudaGetSymbolAddress((void**)&bufB,  g_bufB);
    cudaGetSymbolAddress((void**)&bhi,   g_Bhi);
    cudaGetSymbolAddress((void**)&blo,   g_Blo);

    cudaFuncSetAttribute(gemm_tc_kernel,
                         cudaFuncAttributeMaxDynamicSharedMemorySize, SM_BYTES);

    // weight prep + CSR build
    prep_w_kernel<<<(PREP_TOTAL + 255) / 256, 256>>>(W0, W1, W2, Wm1, Wm2, bhi, blo);
    zero_kernel<<<(NN + 1 + 255) / 256, 256>>>(deg, descs);
    hist_kernel<<<(NE + 255) / 256, 256>>>(dst, deg);
    scanfused_kernel<<<SCAN_BLOCKS, 1024>>>(deg, off, cur, descs);
    scatter_kernel<<<(NE + 255) / 256, 256>>>(src, dst, cur, srcs);

    const int warpBlocks = (NN * 32 + 255) / 256;
    const int gemmBlocks = (NN + 127) / 128;   // 391

    // layer 0
    agg_kernel<<<warpBlocks, 256>>>((const float4*)x, off, srcs, (float4*)bufA);
    gemm_tc_kernel<<<gemmBlocks, 256, SM_BYTES>>>(bufA, bhi, blo, b0, bufB, 0, 128, 1,
                                                  0, nullptr, nullptr);
    // layer 1
    agg_kernel<<<warpBlocks, 256>>>((const float4*)bufB, off, srcs, (float4*)bufA);
    gemm_tc_kernel<<<gemmBlocks, 256, SM_BYTES>>>(bufA, bhi, blo, b1, bufB, 1, 128, 1,
                                                  0, nullptr, nullptr);
    // layer 2
    agg_kernel<<<warpBlocks, 256>>>((const float4*)bufB, off, srcs, (float4*)bufA);
    gemm_tc_kernel<<<gemmBlocks, 256, SM_BYTES>>>(bufA, bhi, blo, b2, bufB, 2, 128, 1,
                                                  0, nullptr, nullptr);
    // MLP hidden (both column tiles) + head, fully fused; logits straight to d_out
    gemm_tc_kernel<<<gemmBlocks, 256, SM_BYTES>>>(bufB, bhi, blo, bm1, bufA, 3, 256, 2,
                                                  1, (float*)d_out, bm2);
}